// round 3
// baseline (speedup 1.0000x reference)
#include <cuda_runtime.h>
#include <cuda_bf16.h>
#include <math.h>

// Problem dims (fixed by dataset)
#define BB 4
#define CC 16
#define HH 512
#define WW 1024

// Scratch (device globals — no allocation allowed)
__device__ unsigned int g_dirs[BB * HH * WW];   // 2 bits per class, 16 classes -> u32 per pixel
__device__ double g_partial[512];               // per-block partial sums (deterministic slots)

// ---------------------------------------------------------------------------
// Kernel 1: per-pixel packed dirs for all 16 classes.
// Composite 5x5 stencils of the one-hot mask (interior-exact):
//   gxx = S[i]*D2[j], gxy = E[i]*E[j], gyy = D2[i]*S[j]   (all /64, cancels in ratio)
// Packed accumulator per class: count(5b) | gxx+12n(9b) | gxy+4n(8b) | gyy+12n(9b)
// ---------------------------------------------------------------------------
#define K1_TX 64
#define K1_TY 16
#define K1_THREADS 256

__global__ __launch_bounds__(K1_THREADS) void dirs_kernel(const int* __restrict__ labels) {
    __shared__ unsigned char slbl[20 * 68];
    __shared__ unsigned int acc[16 * K1_THREADS];

    const int tid = threadIdx.x;
    const int b = blockIdx.z;
    const int y0 = blockIdx.y * K1_TY;
    const int x0 = blockIdx.x * K1_TX;
    const int* lb = labels + b * HH * WW;

    for (int i = tid; i < 20 * 68; i += K1_THREADS) {
        int r = i / 68, cc2 = i - r * 68;
        int gy = min(max(y0 - 2 + r, 0), HH - 1);
        int gx = min(max(x0 - 2 + cc2, 0), WW - 1);
        slbl[i] = (unsigned char)(lb[gy * WW + gx] & 15);  // mask: never OOB in acc
    }
    __syncthreads();

    const int px = tid & 63;
    const int py0 = tid >> 6;  // 0..3

    const int S[5]  = {1, 4, 6, 4, 1};
    const int D2[5] = {1, 0, -2, 0, 1};
    const int E[5]  = {-1, -2, 0, 2, 1};

    for (int k = 0; k < 4; k++) {
        int py = py0 + 4 * k;   // local row 0..15

        // zero private accumulator column
        #pragma unroll
        for (int c = 0; c < 16; c++) acc[c * K1_THREADS + tid] = 0u;

        // load 5x5 label window
        unsigned int l[25];
        #pragma unroll
        for (int i = 0; i < 5; i++)
            #pragma unroll
            for (int j = 0; j < 5; j++)
                l[i * 5 + j] = slbl[(py + i) * 68 + (px + j)];

        // scatter-accumulate packed weights per class
        #pragma unroll
        for (int i = 0; i < 5; i++) {
            #pragma unroll
            for (int j = 0; j < 5; j++) {
                int w1 = S[i] * D2[j];
                int w2 = E[i] * E[j];
                int w3 = D2[i] * S[j];
                unsigned int P = 1u | ((unsigned int)(w1 + 12) << 5)
                                    | ((unsigned int)(w2 + 4) << 14)
                                    | ((unsigned int)(w3 + 12) << 22);
                acc[l[i * 5 + j] * K1_THREADS + tid] += P;
            }
        }

        // decode + classify direction per class
        unsigned int word = 0u;
        #pragma unroll
        for (int c = 0; c < 16; c++) {
            unsigned int v = acc[c * K1_THREADS + tid];
            int n   = (int)(v & 31u);
            int gxx = (int)((v >> 5) & 511u) - 12 * n;
            int gxy = (int)((v >> 14) & 255u) - 4 * n;
            int gyy = (int)((v >> 22) & 511u) - 12 * n;
            // sign(-gxy + EPS): +1 unless gxy > 0
            float sgn = (gxy > 0) ? -1.0f : 1.0f;
            // t = gyy*sgn/(gxx + 64*EPS)   (x64 scaling cancels)
            float t = (float)gyy * sgn / ((float)gxx + 7.6293945e-6f);
            float at = fabsf(t);
            int d;
            if (at < 0.32491970f)       d = 0;                       // round -> 0
            else if (at < 1.37638190f)  d = (t > 0.0f) ? 1 : 0;      // round -> +-1
            else                        d = (t > 0.0f) ? 2 : 3;      // round -> +-2
            word |= (unsigned int)d << (2 * c);
        }
        g_dirs[(b * HH + (y0 + py)) * WW + (x0 + px)] = word;
    }
}

// ---------------------------------------------------------------------------
// Kernel 2: main NMS sum. 64x64 tile per (b, tile), loop over 16 classes.
// exp computed once per element into shared. dirs 1 and 3 share offsets.
// ---------------------------------------------------------------------------
#define K2_T 64
#define K2_THREADS 512
#define SH_STRIDE 68  // 67 cols padded

__global__ __launch_bounds__(K2_THREADS) void nms_kernel(const float* __restrict__ pred) {
    __shared__ float sh[67 * SH_STRIDE];
    __shared__ double warpsum[16];

    const int tid = threadIdx.x;
    const int b = blockIdx.z;
    const int y0 = blockIdx.y * K2_T;
    const int x0 = blockIdx.x * K2_T;
    const int px = tid & 63;
    const int py0 = tid >> 6;  // 0..7

    // per-thread dirs words (reused across all 16 classes)
    unsigned int dw[8];
    #pragma unroll
    for (int k = 0; k < 8; k++) {
        int py = py0 + 8 * k;
        dw[k] = g_dirs[(b * HH + y0 + py) * WW + (x0 + px)];
    }

    float accf = 0.0f;

    for (int c = 0; c < 16; c++) {
        const float* p = pred + (((long long)b * CC + c) * HH) * WW;
        __syncthreads();
        for (int i = tid; i < 67 * 67; i += K2_THREADS) {
            int r = i / 67, cc2 = i - r * 67;
            int gy = min(max(y0 - 2 + r, 0), HH - 1);
            int gx = min(max(x0 - 2 + cc2, 0), WW - 1);
            sh[r * SH_STRIDE + cc2] = __expf(p[gy * WW + gx]);
        }
        __syncthreads();

        #pragma unroll
        for (int k = 0; k < 8; k++) {
            int py = py0 + 8 * k;
            int gy = y0 + py, gx = x0 + px;
            if (gy < 2 || gy >= HH - 2 || gx < 2 || gx >= WW - 2) continue;
            int sy = py + 2, sx = px + 2;
            int d = (dw[k] >> (2 * c)) & 3;
            float center = sh[sy * SH_STRIDE + sx];
            float denom;
            if (d == 0) {
                denom = sh[sy * SH_STRIDE + sx - 2] + sh[sy * SH_STRIDE + sx - 1]
                      + center + sh[sy * SH_STRIDE + sx + 1];
            } else if (d == 2) {
                denom = sh[(sy - 2) * SH_STRIDE + sx] + sh[(sy - 1) * SH_STRIDE + sx]
                      + center + sh[(sy + 1) * SH_STRIDE + sx];
            } else {  // 1 and 3: identical offset set (-2,1),(-1,0),(0,-1),(1,-2)
                denom = sh[(sy - 2) * SH_STRIDE + sx + 1] + sh[(sy - 1) * SH_STRIDE + sx]
                      + sh[sy * SH_STRIDE + sx - 1] + sh[(sy + 1) * SH_STRIDE + sx - 2];
            }
            accf += __fdividef(center, denom);
        }
    }

    // deterministic block reduction -> fixed partial slot
    double v = (double)accf;
    #pragma unroll
    for (int o = 16; o > 0; o >>= 1) v += __shfl_down_sync(0xffffffffu, v, o);
    if ((tid & 31) == 0) warpsum[tid >> 5] = v;
    __syncthreads();
    if (tid < 16) {
        double w = warpsum[tid];
        #pragma unroll
        for (int o = 8; o > 0; o >>= 1) w += __shfl_down_sync(0xffffu, w, o);
        if (tid == 0) g_partial[blockIdx.x + 16 * blockIdx.y + 128 * blockIdx.z] = w;
    }
}

// ---------------------------------------------------------------------------
// Kernel 3: deterministic final reduction of 512 partials
// ---------------------------------------------------------------------------
__global__ void finalize_kernel(float* __restrict__ out) {
    __shared__ double s[512];
    int tid = threadIdx.x;
    s[tid] = g_partial[tid];
    __syncthreads();
    for (int off = 256; off > 0; off >>= 1) {
        if (tid < off) s[tid] += s[tid + off];
        __syncthreads();
    }
    if (tid == 0) out[0] = (float)s[0];
}

extern "C" void kernel_launch(void* const* d_in, const int* in_sizes, int n_in,
                              void* d_out, int out_size) {
    const float* pred = (const float*)d_in[0];   // [4,16,512,1024] f32
    const int* labels = (const int*)d_in[1];     // [4,512,1024] int32 (jax default int)
    float* out = (float*)d_out;

    dirs_kernel<<<dim3(WW / K1_TX, HH / K1_TY, BB), K1_THREADS>>>(labels);
    nms_kernel<<<dim3(WW / K2_T, HH / K2_T, BB), K2_THREADS>>>(pred);
    finalize_kernel<<<1, 512>>>(out);
}

// round 4
// speedup vs baseline: 1.4775x; 1.4775x over previous
#include <cuda_runtime.h>
#include <cuda_bf16.h>
#include <math.h>

#define BB 4
#define CC 16
#define HH 512
#define WW 1024

__device__ unsigned int g_dirs[BB * HH * WW];   // 2 bits/class, 16 classes per pixel
__device__ double g_partial[512];

#define ONES 0x0101010101010101ULL

// ---------------------------------------------------------------------------
// Kernel 1: packed byte-SIMD separable stencils + LUT classify.
// Tile 64 wide x 32 tall, 256 threads = 64 cols x 4 row-groups (8 rows each).
// ---------------------------------------------------------------------------
__global__ __launch_bounds__(256) void dirs_kernel(const int* __restrict__ labels) {
    __shared__ unsigned char slbl[36 * 68];
    __shared__ unsigned char lutd[65 * 65];

    const int tid = threadIdx.x;
    const int b = blockIdx.z;
    const int y0 = blockIdx.y * 32;
    const int x0 = blockIdx.x * 64;
    const int* lb = labels + b * HH * WW;

    // LUT: identical fp32 classification math as validated R3 kernel.
    // Entry (i,j): gxx = i-32, gyy = j-32, sgn=+1 branch. gxy>0 handled by j -> 64-j.
    for (int idx = tid; idx < 65 * 65; idx += 256) {
        int i = idx / 65, j = idx - i * 65;
        float gxxf = (float)(i - 32);
        float gyyf = (float)(j - 32);
        float t = gyyf / (gxxf + 7.6293945e-6f);
        float at = fabsf(t);
        int d;
        if (at < 0.32491970f)      d = 0;
        else if (at < 1.37638190f) d = (t > 0.0f) ? 1 : 0;
        else                       d = (t > 0.0f) ? 2 : 3;
        lutd[idx] = (unsigned char)d;
    }

    for (int i = tid; i < 36 * 68; i += 256) {
        int r = i / 68, c = i - r * 68;
        int gy = min(max(y0 - 2 + r, 0), HH - 1);
        int gx = min(max(x0 - 2 + c, 0), WW - 1);
        slbl[i] = (unsigned char)(lb[gy * WW + gx] & 15);
    }
    __syncthreads();

    const int px = tid & 63;
    const int tg = tid >> 6;
    const int j0 = tg * 8;   // first local output row of this thread (0..24)

    // Ring of 5 horizontal filter rows (slot = local_halo_row % 5 relative to j0)
    unsigned long long D2lo[5], D2hi[5], Slo[5], Shi[5], Elo[5], Ehi[5];

#define HROW(HR, SLOT)                                                          \
    do {                                                                        \
        const unsigned char* _row = &slbl[(HR) * 68 + px];                      \
        unsigned long long olo[5], ohi[5];                                      \
        _Pragma("unroll")                                                       \
        for (int q = 0; q < 5; q++) {                                           \
            int l = _row[q];                                                    \
            unsigned long long bit = 1ULL << ((l & 7) * 8);                     \
            olo[q] = (l < 8) ? bit : 0ULL;                                      \
            ohi[q] = (l < 8) ? 0ULL : bit;                                      \
        }                                                                       \
        Slo[SLOT]  = olo[0] + olo[4] + ((olo[1] + olo[3]) << 2)                 \
                   + (olo[2] << 2) + (olo[2] << 1);                             \
        Shi[SLOT]  = ohi[0] + ohi[4] + ((ohi[1] + ohi[3]) << 2)                 \
                   + (ohi[2] << 2) + (ohi[2] << 1);                             \
        D2lo[SLOT] = olo[0] + olo[4] + ((ONES - olo[2]) << 1);                  \
        D2hi[SLOT] = ohi[0] + ohi[4] + ((ONES - ohi[2]) << 1);                  \
        Elo[SLOT]  = (olo[3] << 1) + olo[4] + 3 * ONES - (olo[0] + (olo[1] << 1)); \
        Ehi[SLOT]  = (ohi[3] << 1) + ohi[4] + 3 * ONES - (ohi[0] + (ohi[1] << 1)); \
    } while (0)

    #pragma unroll
    for (int s = 0; s < 5; s++) HROW(j0 + s, s);

    unsigned int* gd = &g_dirs[(b * HH + y0) * WW + x0 + px];

    #pragma unroll
    for (int j = 0; j < 8; j++) {
        // window slots: local halo rows (j0+j)..(j0+j+4) live in slots (j+i)%5
        const int w0 = (j + 0) % 5, w1 = (j + 1) % 5, w2 = (j + 2) % 5;
        const int w3 = (j + 3) % 5, w4 = (j + 4) % 5;

        // gxx = S (rows) of hD2 : fields = gxx + 32, in [0,64]
        unsigned long long gxxlo = D2lo[w0] + D2lo[w4] + ((D2lo[w1] + D2lo[w3]) << 2)
                                 + (D2lo[w2] << 2) + (D2lo[w2] << 1);
        unsigned long long gxxhi = D2hi[w0] + D2hi[w4] + ((D2hi[w1] + D2hi[w3]) << 2)
                                 + (D2hi[w2] << 2) + (D2hi[w2] << 1);
        // gyy = D2 (rows) of hS : fields = gyy + 32, in [0,64]
        unsigned long long gyylo = Slo[w0] + Slo[w4] + 32 * ONES - (Slo[w2] << 1);
        unsigned long long gyyhi = Shi[w0] + Shi[w4] + 32 * ONES - (Shi[w2] << 1);
        // gxy = E (rows) of hE : fields = gxy + 18, in [0,36] (E bias cancels, sum(E)=0)
        unsigned long long gxylo = (Elo[w3] << 1) + Elo[w4] + 18 * ONES
                                 - (Elo[w0] + (Elo[w1] << 1));
        unsigned long long gxyhi = (Ehi[w3] << 1) + Ehi[w4] + 18 * ONES
                                 - (Ehi[w0] + (Ehi[w1] << 1));

        unsigned int word = 0u;
        #pragma unroll
        for (int c = 0; c < 16; c++) {
            const int sh8 = (c & 7) * 8;
            int gxxb = (int)(((c < 8 ? gxxlo : gxxhi) >> sh8) & 255u);
            int gyyb = (int)(((c < 8 ? gyylo : gyyhi) >> sh8) & 255u);
            int gxyb = (int)(((c < 8 ? gxylo : gxyhi) >> sh8) & 255u);
            int jj = (gxyb > 18) ? (64 - gyyb) : gyyb;   // gxy>0  <=>  flip gyy sign
            unsigned int d = lutd[gxxb * 65 + jj];
            word |= d << (2 * c);
        }
        gd[(j0 + j) * WW] = word;

        if (j < 7) HROW(j0 + j + 5, j % 5);
    }
#undef HROW
}

// ---------------------------------------------------------------------------
// Kernel 2: NMS sum, 64x64 tile, branchless tap addressing (no divergence).
// ---------------------------------------------------------------------------
#define K2_THREADS 512
#define SH_STRIDE 68

__global__ __launch_bounds__(K2_THREADS) void nms_kernel(const float* __restrict__ pred) {
    __shared__ float sh[67 * SH_STRIDE];
    __shared__ double warpsum[16];

    const int tid = threadIdx.x;
    const int b = blockIdx.z;
    const int y0 = blockIdx.y * 64;
    const int x0 = blockIdx.x * 64;
    const int px = tid & 63;
    const int py0 = tid >> 6;  // 0..7

    unsigned int dw[8];
    #pragma unroll
    for (int k = 0; k < 8; k++)
        dw[k] = g_dirs[(b * HH + y0 + py0 + 8 * k) * WW + (x0 + px)];

    float accf = 0.0f;

    for (int c = 0; c < 16; c++) {
        const float* p = pred + (((long long)b * CC + c) * HH) * WW;
        __syncthreads();
        for (int i = tid; i < 67 * 67; i += K2_THREADS) {
            int r = i / 67, cc2 = i - r * 67;
            int gy = min(max(y0 - 2 + r, 0), HH - 1);
            int gx = min(max(x0 - 2 + cc2, 0), WW - 1);
            sh[r * SH_STRIDE + cc2] = __expf(p[gy * WW + gx]);
        }
        __syncthreads();

        #pragma unroll
        for (int k = 0; k < 8; k++) {
            int py = py0 + 8 * k;
            int gy = y0 + py, gx = x0 + px;
            if (gy < 2 || gy >= HH - 2 || gx < 2 || gx >= WW - 2) continue;
            int base = (py + 2) * SH_STRIDE + (px + 2);
            int d = (dw[k] >> (2 * c)) & 3;
            int e = (d == 3) ? 1 : d;          // dirs 1 & 3 share one offset set
            float center = sh[base];
            float denom = 0.0f;
            #pragma unroll
            for (int k2 = 0; k2 < 4; k2++) {
                int off = (e == 0) ? (k2 - 2)
                        : ((e == 2) ? SH_STRIDE * (k2 - 2)
                                    : ((SH_STRIDE - 1) * k2 - (2 * SH_STRIDE - 1)));
                denom += sh[base + off];
            }
            accf += __fdividef(center, denom);
        }
    }

    double v = (double)accf;
    #pragma unroll
    for (int o = 16; o > 0; o >>= 1) v += __shfl_down_sync(0xffffffffu, v, o);
    if ((tid & 31) == 0) warpsum[tid >> 5] = v;
    __syncthreads();
    if (tid < 16) {
        double w = warpsum[tid];
        #pragma unroll
        for (int o = 8; o > 0; o >>= 1) w += __shfl_down_sync(0xffffu, w, o);
        if (tid == 0) g_partial[blockIdx.x + 16 * blockIdx.y + 128 * blockIdx.z] = w;
    }
}

__global__ void finalize_kernel(float* __restrict__ out) {
    __shared__ double s[512];
    int tid = threadIdx.x;
    s[tid] = g_partial[tid];
    __syncthreads();
    for (int off = 256; off > 0; off >>= 1) {
        if (tid < off) s[tid] += s[tid + off];
        __syncthreads();
    }
    if (tid == 0) out[0] = (float)s[0];
}

extern "C" void kernel_launch(void* const* d_in, const int* in_sizes, int n_in,
                              void* d_out, int out_size) {
    const float* pred = (const float*)d_in[0];   // [4,16,512,1024] f32
    const int* labels = (const int*)d_in[1];     // [4,512,1024] int32
    float* out = (float*)d_out;

    dirs_kernel<<<dim3(16, 16, 4), 256>>>(labels);
    nms_kernel<<<dim3(16, 8, 4), 512>>>(pred);
    finalize_kernel<<<1, 512>>>(out);
}